// round 3
// baseline (speedup 1.0000x reference)
#include <cuda_runtime.h>
#include <cuda_bf16.h>

// Problem shape (fixed by setup_inputs): b=4, h=8, L=256, d=64
#define L_SEQ 256
#define DHEAD 64
#define N_BH  32   // b*h

#define MASK_VAL (-4294967295.0f)   // -2^32 + 1

__device__ __forceinline__ float4 ldcs4(const float4* p) { return __ldcs(p); }
__device__ __forceinline__ void stcs1(float* p, float v) { __stcs(p, v); }

__global__ __launch_bounds__(256, 5)
void taspd_kernel(const float* __restrict__ Q,
                  const float* __restrict__ K,
                  const float* __restrict__ V,
                  const float* __restrict__ tK,
                  const float* __restrict__ tV,
                  const float* __restrict__ attn_mask,
                  const unsigned char* __restrict__ pad_mask,
                  float* __restrict__ O,
                  float* __restrict__ attnW)
{
    const int bid = blockIdx.x;          // 0 .. 8191
    const int q   = bid & (L_SEQ - 1);
    const int bh  = bid >> 8;            // 0 .. 31
    const int b   = bh >> 3;             // h = 8
    const int tid = threadIdx.x;

    __shared__ float sE[L_SEQ];          // energy, then softmax weights
    __shared__ float sRed[16 * DHEAD];   // phase-2 partial sums
    __shared__ float sScr[8];            // cross-warp reduce scratch

    const float* Qrow  = Q + ((size_t)bh * L_SEQ + q) * DHEAD;
    const float* Kbase = K + (size_t)bh * L_SEQ * DHEAD;
    const float* Vbase = V + (size_t)bh * L_SEQ * DHEAD;
    const size_t tbase = ((size_t)bh * L_SEQ + q) * (size_t)L_SEQ * DHEAD;
    const float* tKrow = tK + tbase;     // [L_SEQ][DHEAD] slice
    const float* tVrow = tV + tbase;

    const int lane16 = tid & 15;         // 16 lanes cover d=64 as float4
    const int grp    = tid >> 4;         // 16 groups cover k

    // ---------------- Phase 1: energy[k] = Q . (K_k + tK_k) ----------------
    {
        float4 q4 = reinterpret_cast<const float4*>(Qrow)[lane16];
        #pragma unroll 4
        for (int it = 0; it < 16; ++it) {
            const int k = it * 16 + grp;
            float4 kv = reinterpret_cast<const float4*>(Kbase + (size_t)k * DHEAD)[lane16];
            float4 tk = ldcs4(reinterpret_cast<const float4*>(tKrow + (size_t)k * DHEAD) + lane16);
            float p = q4.x * (kv.x + tk.x) + q4.y * (kv.y + tk.y)
                    + q4.z * (kv.z + tk.z) + q4.w * (kv.w + tk.w);
            // reduce across the 16-lane segment (xor stays inside segment)
            p += __shfl_xor_sync(0xffffffffu, p, 8);
            p += __shfl_xor_sync(0xffffffffu, p, 4);
            p += __shfl_xor_sync(0xffffffffu, p, 2);
            p += __shfl_xor_sync(0xffffffffu, p, 1);
            if (lane16 == 0) {
                float e = p * 0.125f + attn_mask[q * L_SEQ + k];   // /sqrt(64)
                if (pad_mask[b * L_SEQ + k]) e = MASK_VAL;
                sE[k] = e;
            }
        }
    }
    __syncthreads();

    // ---------------- Softmax over k (tid owns k = tid) ----------------
    float e = sE[tid];
    float m = e;
    #pragma unroll
    for (int off = 16; off; off >>= 1)
        m = fmaxf(m, __shfl_xor_sync(0xffffffffu, m, off));
    if ((tid & 31) == 0) sScr[tid >> 5] = m;
    __syncthreads();
    m = sScr[0];
    #pragma unroll
    for (int i = 1; i < 8; ++i) m = fmaxf(m, sScr[i]);
    __syncthreads();                     // protect sScr before reuse

    float ex = __expf(e - m);
    float s = ex;
    #pragma unroll
    for (int off = 16; off; off >>= 1)
        s += __shfl_xor_sync(0xffffffffu, s, off);
    if ((tid & 31) == 0) sScr[tid >> 5] = s;
    __syncthreads();
    s = sScr[0];
    #pragma unroll
    for (int i = 1; i < 8; ++i) s += sScr[i];

    const float w = ex / s;
    sE[tid] = w;                          // own element: no race
    if (attnW)
        stcs1(&attnW[((size_t)bh * L_SEQ + q) * L_SEQ + tid], w);
    __syncthreads();

    // ---------------- Phase 2: O[d] = sum_k w_k * (V_k[d] + tV_k[d]) -------
    // Two k-rows per iteration: 4 independent loads in flight -> higher MLP.
    {
        float4 acc = make_float4(0.f, 0.f, 0.f, 0.f);
        for (int it = 0; it < 8; ++it) {
            const int k0 = it * 32 + grp;          // grp in [0,16)
            const int k1 = k0 + 16;
            float4 v0  = reinterpret_cast<const float4*>(Vbase + (size_t)k0 * DHEAD)[lane16];
            float4 tv0 = ldcs4(reinterpret_cast<const float4*>(tVrow + (size_t)k0 * DHEAD) + lane16);
            float4 v1  = reinterpret_cast<const float4*>(Vbase + (size_t)k1 * DHEAD)[lane16];
            float4 tv1 = ldcs4(reinterpret_cast<const float4*>(tVrow + (size_t)k1 * DHEAD) + lane16);
            const float w0 = sE[k0];
            const float w1 = sE[k1];
            acc.x += w0 * (v0.x + tv0.x) + w1 * (v1.x + tv1.x);
            acc.y += w0 * (v0.y + tv0.y) + w1 * (v1.y + tv1.y);
            acc.z += w0 * (v0.z + tv0.z) + w1 * (v1.z + tv1.z);
            acc.w += w0 * (v0.w + tv0.w) + w1 * (v1.w + tv1.w);
        }
        reinterpret_cast<float4*>(sRed + grp * DHEAD)[lane16] = acc;
        __syncthreads();
        if (tid < DHEAD) {
            float o = 0.f;
            #pragma unroll
            for (int g = 0; g < 16; ++g) o += sRed[g * DHEAD + tid];
            O[((size_t)bh * L_SEQ + q) * DHEAD + tid] = o;
        }
    }
}

extern "C" void kernel_launch(void* const* d_in, const int* in_sizes, int n_in,
                              void* d_out, int out_size)
{
    const float*         Q  = (const float*)d_in[0];
    const float*         K  = (const float*)d_in[1];
    const float*         V  = (const float*)d_in[2];
    const float*         tK = (const float*)d_in[3];
    const float*         tV = (const float*)d_in[4];
    const float*         am = (const float*)d_in[5];
    const unsigned char* pm = (const unsigned char*)d_in[6];

    float* O = (float*)d_out;
    const int o_elems    = N_BH * L_SEQ * DHEAD;   // 2,097,152
    const int attn_elems = N_BH * L_SEQ * L_SEQ;   // 8,388,608
    float* attnW = (out_size >= o_elems + attn_elems) ? O + o_elems : nullptr;

    taspd_kernel<<<N_BH * L_SEQ, 256>>>(Q, K, V, tK, tV, am, pm, O, attnW);
}

// round 4
// speedup vs baseline: 1.0790x; 1.0790x over previous
#include <cuda_runtime.h>
#include <cuda_bf16.h>

// Problem shape (fixed by setup_inputs): b=4, h=8, L=256, d=64
#define L_SEQ 256
#define DHEAD 64
#define N_BH  32   // b*h

#define MASK_VAL (-4294967295.0f)   // -2^32 + 1

__global__ __launch_bounds__(256, 4)
void taspd_kernel(const float* __restrict__ Q,
                  const float* __restrict__ K,
                  const float* __restrict__ V,
                  const float* __restrict__ tK,
                  const float* __restrict__ tV,
                  const float* __restrict__ attn_mask,
                  const unsigned char* __restrict__ pad_mask,
                  float* __restrict__ O,
                  float* __restrict__ attnW)
{
    const int bid = blockIdx.x;          // 0 .. 8191
    const int q   = bid & (L_SEQ - 1);
    const int bh  = bid >> 8;            // 0 .. 31
    const int b   = bh >> 3;             // h = 8
    const int tid = threadIdx.x;

    __shared__ float sE[L_SEQ];          // energy, then softmax weights
    __shared__ float sRed[16 * DHEAD];   // phase-2 partial sums
    __shared__ float sScr[8];            // cross-warp reduce scratch

    const float* Qrow  = Q + ((size_t)bh * L_SEQ + q) * DHEAD;
    const float* Kbase = K + (size_t)bh * L_SEQ * DHEAD;
    const float* Vbase = V + (size_t)bh * L_SEQ * DHEAD;
    const size_t tbase = ((size_t)bh * L_SEQ + q) * (size_t)L_SEQ * DHEAD;
    const float* tKrow = tK + tbase;     // [L_SEQ][DHEAD] slice
    const float* tVrow = tV + tbase;

    const int lane16 = tid & 15;         // 16 lanes cover d=64 as float4
    const int grp    = tid >> 4;         // 16 groups cover k

    // ---------------- Phase 1: energy[k] = Q . (K_k + tK_k) ----------------
    {
        float4 q4 = reinterpret_cast<const float4*>(Qrow)[lane16];
        #pragma unroll 4
        for (int it = 0; it < 16; ++it) {
            const int k = it * 16 + grp;
            float4 kv = reinterpret_cast<const float4*>(Kbase + (size_t)k * DHEAD)[lane16];
            float4 tk = __ldcs(reinterpret_cast<const float4*>(tKrow + (size_t)k * DHEAD) + lane16);
            float p = q4.x * (kv.x + tk.x) + q4.y * (kv.y + tk.y)
                    + q4.z * (kv.z + tk.z) + q4.w * (kv.w + tk.w);
            // reduce across the 16-lane segment (xor stays inside segment)
            p += __shfl_xor_sync(0xffffffffu, p, 8);
            p += __shfl_xor_sync(0xffffffffu, p, 4);
            p += __shfl_xor_sync(0xffffffffu, p, 2);
            p += __shfl_xor_sync(0xffffffffu, p, 1);
            if (lane16 == 0) {
                float e = p * 0.125f + attn_mask[q * L_SEQ + k];   // /sqrt(64)
                if (pad_mask[b * L_SEQ + k]) e = MASK_VAL;
                sE[k] = e;
            }
        }
    }
    __syncthreads();

    // ---------------- Softmax over k (tid owns k = tid) ----------------
    float e = sE[tid];
    float m = e;
    #pragma unroll
    for (int off = 16; off; off >>= 1)
        m = fmaxf(m, __shfl_xor_sync(0xffffffffu, m, off));
    if ((tid & 31) == 0) sScr[tid >> 5] = m;
    __syncthreads();
    m = sScr[0];
    #pragma unroll
    for (int i = 1; i < 8; ++i) m = fmaxf(m, sScr[i]);
    __syncthreads();                     // protect sScr before reuse

    float ex = __expf(e - m);
    float s = ex;
    #pragma unroll
    for (int off = 16; off; off >>= 1)
        s += __shfl_xor_sync(0xffffffffu, s, off);
    if ((tid & 31) == 0) sScr[tid >> 5] = s;
    __syncthreads();
    s = sScr[0];
    #pragma unroll
    for (int i = 1; i < 8; ++i) s += sScr[i];

    const float w = ex / s;
    sE[tid] = w;                          // own element: no race
    if (attnW)
        __stcs(&attnW[((size_t)bh * L_SEQ + q) * L_SEQ + tid], w);
    __syncthreads();

    // ---------------- Phase 2: O[d] = sum_k w_k * (V_k[d] + tV_k[d]) -------
    // Two k-rows per iteration: 4 independent loads in flight -> higher MLP.
    {
        float4 acc = make_float4(0.f, 0.f, 0.f, 0.f);
        #pragma unroll 2
        for (int it = 0; it < 8; ++it) {
            const int k0 = it * 32 + grp;          // grp in [0,16)
            const int k1 = k0 + 16;
            float4 v0  = reinterpret_cast<const float4*>(Vbase + (size_t)k0 * DHEAD)[lane16];
            float4 tv0 = __ldcs(reinterpret_cast<const float4*>(tVrow + (size_t)k0 * DHEAD) + lane16);
            float4 v1  = reinterpret_cast<const float4*>(Vbase + (size_t)k1 * DHEAD)[lane16];
            float4 tv1 = __ldcs(reinterpret_cast<const float4*>(tVrow + (size_t)k1 * DHEAD) + lane16);
            const float w0 = sE[k0];
            const float w1 = sE[k1];
            acc.x += w0 * (v0.x + tv0.x) + w1 * (v1.x + tv1.x);
            acc.y += w0 * (v0.y + tv0.y) + w1 * (v1.y + tv1.y);
            acc.z += w0 * (v0.z + tv0.z) + w1 * (v1.z + tv1.z);
            acc.w += w0 * (v0.w + tv0.w) + w1 * (v1.w + tv1.w);
        }
        reinterpret_cast<float4*>(sRed + grp * DHEAD)[lane16] = acc;
        __syncthreads();
        if (tid < DHEAD) {
            float o = 0.f;
            #pragma unroll
            for (int g = 0; g < 16; ++g) o += sRed[g * DHEAD + tid];
            O[((size_t)bh * L_SEQ + q) * DHEAD + tid] = o;
        }
    }
}

extern "C" void kernel_launch(void* const* d_in, const int* in_sizes, int n_in,
                              void* d_out, int out_size)
{
    const float*         Q  = (const float*)d_in[0];
    const float*         K  = (const float*)d_in[1];
    const float*         V  = (const float*)d_in[2];
    const float*         tK = (const float*)d_in[3];
    const float*         tV = (const float*)d_in[4];
    const float*         am = (const float*)d_in[5];
    const unsigned char* pm = (const unsigned char*)d_in[6];

    float* O = (float*)d_out;
    const int o_elems    = N_BH * L_SEQ * DHEAD;   // 2,097,152
    const int attn_elems = N_BH * L_SEQ * L_SEQ;   // 8,388,608
    float* attnW = (out_size >= o_elems + attn_elems) ? O + o_elems : nullptr;

    taspd_kernel<<<N_BH * L_SEQ, 256>>>(Q, K, V, tK, tV, am, pm, O, attnW);
}

// round 6
// speedup vs baseline: 1.1409x; 1.0574x over previous
#include <cuda_runtime.h>
#include <cuda_bf16.h>

// Problem shape (fixed by setup_inputs): b=4, h=8, L=256, d=64
#define L_SEQ 256
#define DHEAD 64
#define N_BH  32   // b*h

#define MASK_VAL (-4294967295.0f)   // -2^32 + 1

__global__ __launch_bounds__(256, 3)
void taspd_kernel(const float* __restrict__ Q,
                  const float* __restrict__ K,
                  const float* __restrict__ V,
                  const float* __restrict__ tK,
                  const float* __restrict__ tV,
                  const float* __restrict__ attn_mask,
                  const unsigned char* __restrict__ pad_mask,
                  float* __restrict__ O,
                  float* __restrict__ attnW)
{
    const int bid = blockIdx.x;          // 0 .. 8191
    const int q   = bid & (L_SEQ - 1);
    const int bh  = bid >> 8;            // 0 .. 31
    const int b   = bh >> 3;             // h = 8
    const int tid = threadIdx.x;

    __shared__ float sE[L_SEQ];          // energy, then softmax weights
    __shared__ float sRed[16 * DHEAD];   // phase-2 partial sums
    __shared__ float sScr[8];            // cross-warp reduce scratch

    const float* Qrow  = Q + ((size_t)bh * L_SEQ + q) * DHEAD;
    const float* Kbase = K + (size_t)bh * L_SEQ * DHEAD;
    const float* Vbase = V + (size_t)bh * L_SEQ * DHEAD;
    const size_t tbase = ((size_t)bh * L_SEQ + q) * (size_t)L_SEQ * DHEAD;
    const float* tKrow = tK + tbase;     // [L_SEQ][DHEAD] slice
    const float* tVrow = tV + tbase;

    const int lane16 = tid & 15;         // 16 lanes cover d=64 as float4
    const int grp    = tid >> 4;         // 16 groups cover k

    // ---------------- Phase 1: energy[k] = Q . (K_k + tK_k) ----------------
    // 2 k-rows per iteration, all 4 loads issued before any math (MLP=4/thr).
    {
        float4 q4 = reinterpret_cast<const float4*>(Qrow)[lane16];
        #pragma unroll 2
        for (int it = 0; it < 8; ++it) {
            const int k0 = it * 32 + grp;
            const int k1 = k0 + 16;
            float4 kv0 = reinterpret_cast<const float4*>(Kbase + (size_t)k0 * DHEAD)[lane16];
            float4 tk0 = __ldcs(reinterpret_cast<const float4*>(tKrow + (size_t)k0 * DHEAD) + lane16);
            float4 kv1 = reinterpret_cast<const float4*>(Kbase + (size_t)k1 * DHEAD)[lane16];
            float4 tk1 = __ldcs(reinterpret_cast<const float4*>(tKrow + (size_t)k1 * DHEAD) + lane16);

            float p0 = q4.x * (kv0.x + tk0.x) + q4.y * (kv0.y + tk0.y)
                     + q4.z * (kv0.z + tk0.z) + q4.w * (kv0.w + tk0.w);
            float p1 = q4.x * (kv1.x + tk1.x) + q4.y * (kv1.y + tk1.y)
                     + q4.z * (kv1.z + tk1.z) + q4.w * (kv1.w + tk1.w);
            // reduce across the 16-lane segment (xor stays inside segment)
            #pragma unroll
            for (int off = 8; off; off >>= 1) {
                p0 += __shfl_xor_sync(0xffffffffu, p0, off);
                p1 += __shfl_xor_sync(0xffffffffu, p1, off);
            }
            if (lane16 == 0) {
                float e0 = p0 * 0.125f + attn_mask[q * L_SEQ + k0];   // /sqrt(64)
                float e1 = p1 * 0.125f + attn_mask[q * L_SEQ + k1];
                if (pad_mask[b * L_SEQ + k0]) e0 = MASK_VAL;
                if (pad_mask[b * L_SEQ + k1]) e1 = MASK_VAL;
                sE[k0] = e0;
                sE[k1] = e1;
            }
        }
    }
    __syncthreads();

    // ---------------- Softmax over k (tid owns k = tid) ----------------
    float e = sE[tid];
    float m = e;
    #pragma unroll
    for (int off = 16; off; off >>= 1)
        m = fmaxf(m, __shfl_xor_sync(0xffffffffu, m, off));
    if ((tid & 31) == 0) sScr[tid >> 5] = m;
    __syncthreads();
    m = sScr[0];
    #pragma unroll
    for (int i = 1; i < 8; ++i) m = fmaxf(m, sScr[i]);
    __syncthreads();                     // protect sScr before reuse

    float ex = __expf(e - m);
    float s = ex;
    #pragma unroll
    for (int off = 16; off; off >>= 1)
        s += __shfl_xor_sync(0xffffffffu, s, off);
    if ((tid & 31) == 0) sScr[tid >> 5] = s;
    __syncthreads();
    s = sScr[0];
    #pragma unroll
    for (int i = 1; i < 8; ++i) s += sScr[i];

    const float w = ex / s;
    sE[tid] = w;                          // own element: no race
    if (attnW)
        __stcs(&attnW[((size_t)bh * L_SEQ + q) * L_SEQ + tid], w);
    __syncthreads();

    // ---------------- Phase 2: O[d] = sum_k w_k * (V_k[d] + tV_k[d]) -------
    // 4 k-rows per iteration: 8 independent loads in flight (MLP=8/thr).
    {
        float4 acc = make_float4(0.f, 0.f, 0.f, 0.f);
        #pragma unroll
        for (int it = 0; it < 4; ++it) {
            const int k0 = it * 64 + grp;          // grp in [0,16)
            const int k1 = k0 + 16;
            const int k2 = k0 + 32;
            const int k3 = k0 + 48;
            float4 v0  = reinterpret_cast<const float4*>(Vbase + (size_t)k0 * DHEAD)[lane16];
            float4 tv0 = __ldcs(reinterpret_cast<const float4*>(tVrow + (size_t)k0 * DHEAD) + lane16);
            float4 v1  = reinterpret_cast<const float4*>(Vbase + (size_t)k1 * DHEAD)[lane16];
            float4 tv1 = __ldcs(reinterpret_cast<const float4*>(tVrow + (size_t)k1 * DHEAD) + lane16);
            float4 v2  = reinterpret_cast<const float4*>(Vbase + (size_t)k2 * DHEAD)[lane16];
            float4 tv2 = __ldcs(reinterpret_cast<const float4*>(tVrow + (size_t)k2 * DHEAD) + lane16);
            float4 v3  = reinterpret_cast<const float4*>(Vbase + (size_t)k3 * DHEAD)[lane16];
            float4 tv3 = __ldcs(reinterpret_cast<const float4*>(tVrow + (size_t)k3 * DHEAD) + lane16);
            const float w0 = sE[k0];
            const float w1 = sE[k1];
            const float w2 = sE[k2];
            const float w3 = sE[k3];
            acc.x += w0 * (v0.x + tv0.x) + w1 * (v1.x + tv1.x)
                   + w2 * (v2.x + tv2.x) + w3 * (v3.x + tv3.x);
            acc.y += w0 * (v0.y + tv0.y) + w1 * (v1.y + tv1.y)
                   + w2 * (v2.y + tv2.y) + w3 * (v3.y + tv3.y);
            acc.z += w0 * (v0.z + tv0.z) + w1 * (v1.z + tv1.z)
                   + w2 * (v2.z + tv2.z) + w3 * (v3.z + tv3.z);
            acc.w += w0 * (v0.w + tv0.w) + w1 * (v1.w + tv1.w)
                   + w2 * (v2.w + tv2.w) + w3 * (v3.w + tv3.w);
        }
        reinterpret_cast<float4*>(sRed + grp * DHEAD)[lane16] = acc;
        __syncthreads();
        if (tid < DHEAD) {
            float o = 0.f;
            #pragma unroll
            for (int g = 0; g < 16; ++g) o += sRed[g * DHEAD + tid];
            O[((size_t)bh * L_SEQ + q) * DHEAD + tid] = o;
        }
    }
}

extern "C" void kernel_launch(void* const* d_in, const int* in_sizes, int n_in,
                              void* d_out, int out_size)
{
    const float*         Q  = (const float*)d_in[0];
    const float*         K  = (const float*)d_in[1];
    const float*         V  = (const float*)d_in[2];
    const float*         tK = (const float*)d_in[3];
    const float*         tV = (const float*)d_in[4];
    const float*         am = (const float*)d_in[5];
    const unsigned char* pm = (const unsigned char*)d_in[6];

    float* O = (float*)d_out;
    const int o_elems    = N_BH * L_SEQ * DHEAD;   // 2,097,152
    const int attn_elems = N_BH * L_SEQ * L_SEQ;   // 8,388,608
    float* attnW = (out_size >= o_elems + attn_elems) ? O + o_elems : nullptr;

    taspd_kernel<<<N_BH * L_SEQ, 256>>>(Q, K, V, tK, tV, am, pm, O, attnW);
}

// round 7
// speedup vs baseline: 1.1661x; 1.0221x over previous
#include <cuda_runtime.h>
#include <cuda_bf16.h>

// Problem shape (fixed by setup_inputs): b=4, h=8, L=256, d=64
#define L_SEQ 256
#define DHEAD 64
#define N_BH  32   // b*h

#define MASK_VAL (-4294967295.0f)   // -2^32 + 1

__global__ __launch_bounds__(256, 3)
void taspd_kernel(const float* __restrict__ Q,
                  const float* __restrict__ K,
                  const float* __restrict__ V,
                  const float* __restrict__ tK,
                  const float* __restrict__ tV,
                  const float* __restrict__ attn_mask,
                  const unsigned char* __restrict__ pad_mask,
                  float* __restrict__ O,
                  float* __restrict__ attnW)
{
    const int bid = blockIdx.x;          // 0 .. 8191
    const int q   = bid & (L_SEQ - 1);
    const int bh  = bid >> 8;            // 0 .. 31
    const int b   = bh >> 3;             // h = 8
    const int tid = threadIdx.x;

    __shared__ float sE[L_SEQ];          // energy, then softmax weights
    __shared__ float sRed[16 * DHEAD];   // phase-2 partial sums
    __shared__ float sScr[8];            // cross-warp reduce scratch

    const float* Qrow  = Q + ((size_t)bh * L_SEQ + q) * DHEAD;
    const float* Kbase = K + (size_t)bh * L_SEQ * DHEAD;
    const float* Vbase = V + (size_t)bh * L_SEQ * DHEAD;
    const size_t tbase = ((size_t)bh * L_SEQ + q) * (size_t)L_SEQ * DHEAD;
    const float* tKrow = tK + tbase;     // [L_SEQ][DHEAD] slice
    const float* tVrow = tV + tbase;

    const int lane16 = tid & 15;         // 16 lanes cover d=64 as float4
    const int grp    = tid >> 4;         // 16 groups cover k

    // ---------------- Phase 1: energy[k] = Q . (K_k + tK_k) ----------------
    // 4 k-rows per iteration, all 8 loads issued before any math (MLP=8/thr).
    {
        float4 q4 = reinterpret_cast<const float4*>(Qrow)[lane16];
        #pragma unroll
        for (int it = 0; it < 4; ++it) {
            const int k0 = it * 64 + grp;
            const int k1 = k0 + 16;
            const int k2 = k0 + 32;
            const int k3 = k0 + 48;
            float4 kv0 = reinterpret_cast<const float4*>(Kbase + (size_t)k0 * DHEAD)[lane16];
            float4 tk0 = __ldcs(reinterpret_cast<const float4*>(tKrow + (size_t)k0 * DHEAD) + lane16);
            float4 kv1 = reinterpret_cast<const float4*>(Kbase + (size_t)k1 * DHEAD)[lane16];
            float4 tk1 = __ldcs(reinterpret_cast<const float4*>(tKrow + (size_t)k1 * DHEAD) + lane16);
            float4 kv2 = reinterpret_cast<const float4*>(Kbase + (size_t)k2 * DHEAD)[lane16];
            float4 tk2 = __ldcs(reinterpret_cast<const float4*>(tKrow + (size_t)k2 * DHEAD) + lane16);
            float4 kv3 = reinterpret_cast<const float4*>(Kbase + (size_t)k3 * DHEAD)[lane16];
            float4 tk3 = __ldcs(reinterpret_cast<const float4*>(tKrow + (size_t)k3 * DHEAD) + lane16);

            float p0 = q4.x * (kv0.x + tk0.x) + q4.y * (kv0.y + tk0.y)
                     + q4.z * (kv0.z + tk0.z) + q4.w * (kv0.w + tk0.w);
            float p1 = q4.x * (kv1.x + tk1.x) + q4.y * (kv1.y + tk1.y)
                     + q4.z * (kv1.z + tk1.z) + q4.w * (kv1.w + tk1.w);
            float p2 = q4.x * (kv2.x + tk2.x) + q4.y * (kv2.y + tk2.y)
                     + q4.z * (kv2.z + tk2.z) + q4.w * (kv2.w + tk2.w);
            float p3 = q4.x * (kv3.x + tk3.x) + q4.y * (kv3.y + tk3.y)
                     + q4.z * (kv3.z + tk3.z) + q4.w * (kv3.w + tk3.w);
            // reduce across the 16-lane segment (xor stays inside segment)
            #pragma unroll
            for (int off = 8; off; off >>= 1) {
                p0 += __shfl_xor_sync(0xffffffffu, p0, off);
                p1 += __shfl_xor_sync(0xffffffffu, p1, off);
                p2 += __shfl_xor_sync(0xffffffffu, p2, off);
                p3 += __shfl_xor_sync(0xffffffffu, p3, off);
            }
            if (lane16 == 0) {
                float e0 = p0 * 0.125f + attn_mask[q * L_SEQ + k0];   // /sqrt(64)
                float e1 = p1 * 0.125f + attn_mask[q * L_SEQ + k1];
                float e2 = p2 * 0.125f + attn_mask[q * L_SEQ + k2];
                float e3 = p3 * 0.125f + attn_mask[q * L_SEQ + k3];
                if (pad_mask[b * L_SEQ + k0]) e0 = MASK_VAL;
                if (pad_mask[b * L_SEQ + k1]) e1 = MASK_VAL;
                if (pad_mask[b * L_SEQ + k2]) e2 = MASK_VAL;
                if (pad_mask[b * L_SEQ + k3]) e3 = MASK_VAL;
                sE[k0] = e0;
                sE[k1] = e1;
                sE[k2] = e2;
                sE[k3] = e3;
            }
        }
    }
    __syncthreads();

    // ---------------- Softmax over k (tid owns k = tid) ----------------
    float e = sE[tid];
    float m = e;
    #pragma unroll
    for (int off = 16; off; off >>= 1)
        m = fmaxf(m, __shfl_xor_sync(0xffffffffu, m, off));
    if ((tid & 31) == 0) sScr[tid >> 5] = m;
    __syncthreads();
    m = sScr[0];
    #pragma unroll
    for (int i = 1; i < 8; ++i) m = fmaxf(m, sScr[i]);
    __syncthreads();                     // protect sScr before reuse

    float ex = __expf(e - m);
    float s = ex;
    #pragma unroll
    for (int off = 16; off; off >>= 1)
        s += __shfl_xor_sync(0xffffffffu, s, off);
    if ((tid & 31) == 0) sScr[tid >> 5] = s;
    __syncthreads();
    s = sScr[0];
    #pragma unroll
    for (int i = 1; i < 8; ++i) s += sScr[i];

    const float w = ex / s;
    sE[tid] = w;                          // own element: no race
    if (attnW)
        __stcs(&attnW[((size_t)bh * L_SEQ + q) * L_SEQ + tid], w);
    __syncthreads();

    // ---------------- Phase 2: O[d] = sum_k w_k * (V_k[d] + tV_k[d]) -------
    // 4 k-rows per iteration: 8 independent loads in flight (MLP=8/thr).
    {
        float4 acc = make_float4(0.f, 0.f, 0.f, 0.f);
        #pragma unroll
        for (int it = 0; it < 4; ++it) {
            const int k0 = it * 64 + grp;          // grp in [0,16)
            const int k1 = k0 + 16;
            const int k2 = k0 + 32;
            const int k3 = k0 + 48;
            float4 v0  = reinterpret_cast<const float4*>(Vbase + (size_t)k0 * DHEAD)[lane16];
            float4 tv0 = __ldcs(reinterpret_cast<const float4*>(tVrow + (size_t)k0 * DHEAD) + lane16);
            float4 v1  = reinterpret_cast<const float4*>(Vbase + (size_t)k1 * DHEAD)[lane16];
            float4 tv1 = __ldcs(reinterpret_cast<const float4*>(tVrow + (size_t)k1 * DHEAD) + lane16);
            float4 v2  = reinterpret_cast<const float4*>(Vbase + (size_t)k2 * DHEAD)[lane16];
            float4 tv2 = __ldcs(reinterpret_cast<const float4*>(tVrow + (size_t)k2 * DHEAD) + lane16);
            float4 v3  = reinterpret_cast<const float4*>(Vbase + (size_t)k3 * DHEAD)[lane16];
            float4 tv3 = __ldcs(reinterpret_cast<const float4*>(tVrow + (size_t)k3 * DHEAD) + lane16);
            const float w0 = sE[k0];
            const float w1 = sE[k1];
            const float w2 = sE[k2];
            const float w3 = sE[k3];
            acc.x += w0 * (v0.x + tv0.x) + w1 * (v1.x + tv1.x)
                   + w2 * (v2.x + tv2.x) + w3 * (v3.x + tv3.x);
            acc.y += w0 * (v0.y + tv0.y) + w1 * (v1.y + tv1.y)
                   + w2 * (v2.y + tv2.y) + w3 * (v3.y + tv3.y);
            acc.z += w0 * (v0.z + tv0.z) + w1 * (v1.z + tv1.z)
                   + w2 * (v2.z + tv2.z) + w3 * (v3.z + tv3.z);
            acc.w += w0 * (v0.w + tv0.w) + w1 * (v1.w + tv1.w)
                   + w2 * (v2.w + tv2.w) + w3 * (v3.w + tv3.w);
        }
        reinterpret_cast<float4*>(sRed + grp * DHEAD)[lane16] = acc;
        __syncthreads();
        if (tid < DHEAD) {
            float o = 0.f;
            #pragma unroll
            for (int g = 0; g < 16; ++g) o += sRed[g * DHEAD + tid];
            O[((size_t)bh * L_SEQ + q) * DHEAD + tid] = o;
        }
    }
}

extern "C" void kernel_launch(void* const* d_in, const int* in_sizes, int n_in,
                              void* d_out, int out_size)
{
    const float*         Q  = (const float*)d_in[0];
    const float*         K  = (const float*)d_in[1];
    const float*         V  = (const float*)d_in[2];
    const float*         tK = (const float*)d_in[3];
    const float*         tV = (const float*)d_in[4];
    const float*         am = (const float*)d_in[5];
    const unsigned char* pm = (const unsigned char*)d_in[6];

    float* O = (float*)d_out;
    const int o_elems    = N_BH * L_SEQ * DHEAD;   // 2,097,152
    const int attn_elems = N_BH * L_SEQ * L_SEQ;   // 8,388,608
    float* attnW = (out_size >= o_elems + attn_elems) ? O + o_elems : nullptr;

    taspd_kernel<<<N_BH * L_SEQ, 256>>>(Q, K, V, tK, tV, am, pm, O, attnW);
}